// round 8
// baseline (speedup 1.0000x reference)
#include <cuda_runtime.h>
#include <cstdint>

using ull = unsigned long long;

// ---- all weights in one constant struct (single memcpy node) ----
struct ConstW {
    ull pWq[72];   // [e][p] = (Wq[2p][e], Wq[2p+1][e])
    ull pWk[72];
    ull pWv[72];
    ull pWo[72];
    ull pW1[144];  // [e][p] p<12
    ull pW2[144];  // [f][p] p<6
    ull pbq[6], pbk[6], pbv[6], pbo[6], pb2[6], pb1[12];
};

__constant__ ConstW cw;
__device__ ConstW gStage;

namespace {

constexpr int N = 8;
constexpr int D = 12;
constexpr int F = 24;
constexpr int V = 128;
constexpr int WARPS = 8;
constexpr int THREADS = WARPS * 32;
constexpr int ITEMS_PER_BLOCK = 32;   // 4 items per warp

constexpr int EST = 136;  // embT row stride (words): bank = 8k+v -> conflict-free B frags
constexpr int XST = 40;   // xT row stride (words): bank = 8k+r -> conflict-free A frags

__device__ __forceinline__ ull pack2(float x, float y) {
    ull p; asm("mov.b64 %0, {%1, %2};" : "=l"(p) : "f"(x), "f"(y)); return p;
}
__device__ __forceinline__ void unpack2(ull p, float& x, float& y) {
    asm("mov.b64 {%0, %1}, %2;" : "=f"(x), "=f"(y) : "l"(p));
}
__device__ __forceinline__ void ffma2(ull& d, ull a, ull b) {
    asm("fma.rn.f32x2 %0, %1, %2, %0;" : "+l"(d) : "l"(a), "l"(b));
}
__device__ __forceinline__ uint32_t f2tf(float x) {
    uint32_t u; asm("cvt.rna.tf32.f32 %0, %1;" : "=r"(u) : "f"(x)); return u;
}
__device__ __forceinline__ void mma_tf32(float& c0, float& c1, float& c2, float& c3,
                                         uint32_t a0, uint32_t a1, uint32_t b0) {
    asm("mma.sync.aligned.m16n8k4.row.col.f32.tf32.tf32.f32 "
        "{%0,%1,%2,%3}, {%4,%5}, {%6}, {%0,%1,%2,%3};"
        : "+f"(c0), "+f"(c1), "+f"(c2), "+f"(c3)
        : "r"(a0), "r"(a1), "r"(b0));
}

// ---- pack kernel: gather 12 weight buffers into pair-major staging ----
__global__ void pack_weights_kernel(
    const float* __restrict__ Wq, const float* __restrict__ bq,
    const float* __restrict__ Wk, const float* __restrict__ bk,
    const float* __restrict__ Wv, const float* __restrict__ bv,
    const float* __restrict__ Wo, const float* __restrict__ bo,
    const float* __restrict__ W1, const float* __restrict__ b1,
    const float* __restrict__ W2, const float* __restrict__ b2)
{
    const int t = threadIdx.x;
    for (int i = t; i < 72; i += 256) {
        int e = i / 6, p = i % 6;
        gStage.pWq[i] = pack2(Wq[(2*p) * D + e], Wq[(2*p+1) * D + e]);
        gStage.pWk[i] = pack2(Wk[(2*p) * D + e], Wk[(2*p+1) * D + e]);
        gStage.pWv[i] = pack2(Wv[(2*p) * D + e], Wv[(2*p+1) * D + e]);
        gStage.pWo[i] = pack2(Wo[(2*p) * D + e], Wo[(2*p+1) * D + e]);
    }
    for (int i = t; i < 144; i += 256) {
        int e = i / 12, p = i % 12;
        gStage.pW1[i] = pack2(W1[(2*p) * D + e], W1[(2*p+1) * D + e]);
    }
    for (int i = t; i < 144; i += 256) {
        int f = i / 6, p = i % 6;
        gStage.pW2[i] = pack2(W2[(2*p) * F + f], W2[(2*p+1) * F + f]);
    }
    if (t < 6) {
        gStage.pbq[t] = pack2(bq[2*t], bq[2*t+1]);
        gStage.pbk[t] = pack2(bk[2*t], bk[2*t+1]);
        gStage.pbv[t] = pack2(bv[2*t], bv[2*t+1]);
        gStage.pbo[t] = pack2(bo[2*t], bo[2*t+1]);
        gStage.pb2[t] = pack2(b2[2*t], b2[2*t+1]);
    }
    if (t < 12) gStage.pb1[t] = pack2(b1[2*t], b1[2*t+1]);
}

__global__ __launch_bounds__(THREADS, 3)
void tiny_transformer_kernel(
    const int*   __restrict__ x,
    const float* __restrict__ embed,
    const float* __restrict__ pos,
    const float* __restrict__ blm,
    float* __restrict__ out)
{
    // embT split into tf32 hi/lo (B operand + phase-1 gather source)
    __shared__ uint32_t sEThi[D * EST];
    __shared__ uint32_t sETlo[D * EST];
    __shared__ float sPos[N * D];
    __shared__ float sBlm[V];
    // per-warp final X, transposed [k][row], tf32 hi/lo (A operand)
    __shared__ uint32_t sXThi[WARPS][D * XST];
    __shared__ uint32_t sXTlo[WARPS][D * XST];

    const int tid = threadIdx.x;

    // ---- staging: embed -> transposed tf32 hi/lo ----
    for (int i = tid; i < D * V; i += THREADS) {
        int d = i >> 7, v = i & 127;
        float e = embed[v * D + d];
        uint32_t hi = f2tf(e);
        float lo = e - __uint_as_float(hi);
        sEThi[d * EST + v] = hi;
        sETlo[d * EST + v] = f2tf(lo);
    }
    for (int i = tid; i < N * D; i += THREADS) sPos[i] = pos[i];
    for (int i = tid; i < V; i += THREADS) sBlm[i] = blm[i];
    __syncthreads();

    const int w    = tid >> 5;
    const int lane = tid & 31;
    const int n    = lane & 7;            // token index within item
    const int item_base = blockIdx.x * ITEMS_PER_BLOCK + w * 4;

    // ---- phase 1: X = embed[x] + pos (hi+lo reconstruction) ----
    const int tok = __ldg(&x[item_base * N + lane]);
    float X[D];
    #pragma unroll
    for (int d = 0; d < D; d++) {
        float hi = __uint_as_float(sEThi[d * EST + tok]);
        float lo = __uint_as_float(sETlo[d * EST + tok]);
        X[d] = hi + lo + sPos[n * D + d];
    }

    // ---- phase 2: Q,K,V (packed FFMA2 against constant port) ----
    float Qr[D], Kr[D], Vr[D];
    {
        ull q2[6], k2[6], v2[6];
        #pragma unroll
        for (int p = 0; p < 6; p++) {
            q2[p] = cw.pbq[p]; k2[p] = cw.pbk[p]; v2[p] = cw.pbv[p];
        }
        #pragma unroll
        for (int e = 0; e < D; e++) {
            const ull xp = pack2(X[e], X[e]);
            #pragma unroll
            for (int p = 0; p < 6; p++) {
                ffma2(q2[p], xp, cw.pWq[e * 6 + p]);
                ffma2(k2[p], xp, cw.pWk[e * 6 + p]);
                ffma2(v2[p], xp, cw.pWv[e * 6 + p]);
            }
        }
        #pragma unroll
        for (int p = 0; p < 6; p++) {
            unpack2(q2[p], Qr[2*p], Qr[2*p+1]);
            unpack2(k2[p], Kr[2*p], Kr[2*p+1]);
            unpack2(v2[p], Vr[2*p], Vr[2*p+1]);
        }
    }

    // ---- phase 3: scores via width-8 shuffles ----
    float S[N];
    {
        const float inv_scale = 0.28867513459481287f;  // 1/sqrt(12)
        #pragma unroll
        for (int m = 0; m < N; m++) {
            float acc = 0.f;
            #pragma unroll
            for (int e = 0; e < D; e++)
                acc += Qr[e] * __shfl_sync(0xffffffffu, Kr[e], m, 8);
            S[m] = (m <= n) ? acc * inv_scale : -1e30f;
        }
    }

    // ---- phase 4: softmax ----
    {
        float mx = S[0];
        #pragma unroll
        for (int m = 1; m < N; m++) mx = fmaxf(mx, S[m]);
        float sum = 0.f;
        #pragma unroll
        for (int m = 0; m < N; m++) { S[m] = __expf(S[m] - mx); sum += S[m]; }
        const float inv = 1.f / sum;
        #pragma unroll
        for (int m = 0; m < N; m++) S[m] *= inv;
    }

    // ---- phase 5: A = softmax @ V via shuffles ----
    float A[D];
    #pragma unroll
    for (int e = 0; e < D; e++) A[e] = 0.f;
    #pragma unroll
    for (int m = 0; m < N; m++) {
        const float s = S[m];
        #pragma unroll
        for (int e = 0; e < D; e++)
            A[e] += s * __shfl_sync(0xffffffffu, Vr[e], m, 8);
    }

    // ---- phase 6: X += A @ Wo^T + bo (packed) ----
    {
        ull o2[6];
        #pragma unroll
        for (int p = 0; p < 6; p++) o2[p] = cw.pbo[p];
        #pragma unroll
        for (int e = 0; e < D; e++) {
            const ull ap = pack2(A[e], A[e]);
            #pragma unroll
            for (int p = 0; p < 6; p++)
                ffma2(o2[p], ap, cw.pWo[e * 6 + p]);
        }
        #pragma unroll
        for (int p = 0; p < 6; p++) {
            float u, v; unpack2(o2[p], u, v);
            X[2*p] += u; X[2*p+1] += v;
        }
    }

    // ---- phase 7: H = relu(X @ W1^T + b1) (packed) ----
    float H[F];
    {
        ull h2[12];
        #pragma unroll
        for (int p = 0; p < 12; p++) h2[p] = cw.pb1[p];
        #pragma unroll
        for (int e = 0; e < D; e++) {
            const ull xp = pack2(X[e], X[e]);
            #pragma unroll
            for (int p = 0; p < 12; p++)
                ffma2(h2[p], xp, cw.pW1[e * 12 + p]);
        }
        #pragma unroll
        for (int p = 0; p < 12; p++) {
            float u, v; unpack2(h2[p], u, v);
            H[2*p]   = fmaxf(u, 0.f);
            H[2*p+1] = fmaxf(v, 0.f);
        }
    }

    // ---- phase 8: X += H @ W2^T + b2 (packed) ----
    {
        ull x2[6];
        #pragma unroll
        for (int p = 0; p < 6; p++) x2[p] = cw.pb2[p];
        #pragma unroll
        for (int f = 0; f < F; f++) {
            const ull hp = pack2(H[f], H[f]);
            #pragma unroll
            for (int p = 0; p < 6; p++)
                ffma2(x2[p], hp, cw.pW2[f * 6 + p]);
        }
        #pragma unroll
        for (int p = 0; p < 6; p++) {
            float u, v; unpack2(x2[p], u, v);
            X[2*p] += u; X[2*p+1] += v;
        }
    }

    // ---- handoff: final X -> transposed tf32 hi/lo (row = lane) ----
    #pragma unroll
    for (int d = 0; d < D; d++) {
        uint32_t hi = f2tf(X[d]);
        float lo = X[d] - __uint_as_float(hi);
        sXThi[w][d * XST + lane] = hi;
        sXTlo[w][d * XST + lane] = f2tf(lo);
    }
    __syncwarp();

    // ---- phase 9: logits = Xf @ embT + b_lm via 3xTF32 mma.m16n8k4 ----
    {
        const int g = lane >> 2;        // groupID
        const int t = lane & 3;         // threadID_in_group

        // hoist A fragments: [rowTile][kstep][reg]
        uint32_t ahi[2][3][2], alo[2][3][2];
        #pragma unroll
        for (int rt = 0; rt < 2; rt++) {
            #pragma unroll
            for (int ks = 0; ks < 3; ks++) {
                const int k = ks * 4 + t;
                const int r = rt * 16 + g;
                ahi[rt][ks][0] = sXThi[w][k * XST + r];
                ahi[rt][ks][1] = sXThi[w][k * XST + r + 8];
                alo[rt][ks][0] = sXTlo[w][k * XST + r];
                alo[rt][ks][1] = sXTlo[w][k * XST + r + 8];
            }
        }

        float* obase = out + (size_t)item_base * (N * V);

        #pragma unroll
        for (int ct = 0; ct < 16; ct++) {
            const int col = ct * 8;
            uint32_t bhi[3], blo[3];
            #pragma unroll
            for (int ks = 0; ks < 3; ks++) {
                const int k = ks * 4 + t;
                bhi[ks] = sEThi[k * EST + col + g];
                blo[ks] = sETlo[k * EST + col + g];
            }
            const float2 bias = *reinterpret_cast<const float2*>(&sBlm[col + 2 * t]);

            #pragma unroll
            for (int rt = 0; rt < 2; rt++) {
                float c0 = bias.x, c1 = bias.y, c2 = bias.x, c3 = bias.y;
                #pragma unroll
                for (int ks = 0; ks < 3; ks++) {
                    mma_tf32(c0, c1, c2, c3, alo[rt][ks][0], alo[rt][ks][1], bhi[ks]);
                    mma_tf32(c0, c1, c2, c3, ahi[rt][ks][0], ahi[rt][ks][1], blo[ks]);
                    mma_tf32(c0, c1, c2, c3, ahi[rt][ks][0], ahi[rt][ks][1], bhi[ks]);
                }
                const int r0 = rt * 16 + g;
                const int c0i = col + 2 * t;
                *reinterpret_cast<float2*>(&obase[(size_t)r0 * V + c0i]) =
                    make_float2(c0, c1);
                *reinterpret_cast<float2*>(&obase[(size_t)(r0 + 8) * V + c0i]) =
                    make_float2(c2, c3);
            }
        }
    }
}

}  // namespace

extern "C" void kernel_launch(void* const* d_in, const int* in_sizes, int n_in,
                              void* d_out, int out_size)
{
    const int*   x     = (const int*)  d_in[0];
    const float* embed = (const float*)d_in[1];
    const float* pos   = (const float*)d_in[2];
    const float* blm   = (const float*)d_in[15];
    float* out = (float*)d_out;

    // 1) gather + pair-pack all weights into staging (one kernel node)
    pack_weights_kernel<<<1, 256>>>(
        (const float*)d_in[3],  (const float*)d_in[4],
        (const float*)d_in[5],  (const float*)d_in[6],
        (const float*)d_in[7],  (const float*)d_in[8],
        (const float*)d_in[9],  (const float*)d_in[10],
        (const float*)d_in[11], (const float*)d_in[12],
        (const float*)d_in[13], (const float*)d_in[14]);

    // 2) one D2D copy staging -> constant bank (one memcpy node)
    void *dstC, *srcG;
    cudaGetSymbolAddress(&dstC, cw);
    cudaGetSymbolAddress(&srcG, gStage);
    cudaMemcpyAsync(dstC, srcG, sizeof(ConstW), cudaMemcpyDeviceToDevice);

    // 3) main kernel
    const int batch  = in_sizes[0] / N;              // 32768
    const int blocks = batch / ITEMS_PER_BLOCK;      // 1024

    tiny_transformer_kernel<<<blocks, THREADS>>>(x, embed, pos, blm, out);
}

// round 9
// speedup vs baseline: 1.2109x; 1.2109x over previous
#include <cuda_runtime.h>
#include <cstdint>

using ull = unsigned long long;

// ---- all weights in one constant struct (single memcpy node) ----
struct ConstW {
    ull pWq[72];   // [e][p] = (Wq[2p][e], Wq[2p+1][e])
    ull pWk[72];
    ull pWv[72];
    ull pWo[72];
    ull pW1[144];  // [e][p] p<12
    ull pW2[144];  // [f][p] p<6
    ull pbq[6], pbk[6], pbv[6], pbo[6], pb2[6], pb1[12];
};

__constant__ ConstW cw;
__device__ ConstW gStage;

namespace {

constexpr int N = 8;
constexpr int D = 12;
constexpr int F = 24;
constexpr int V = 128;
constexpr int WARPS = 8;
constexpr int THREADS = WARPS * 32;
constexpr int ITEMS_PER_BLOCK = 32;   // 4 items per warp

#define F4C(p) (*reinterpret_cast<const float4*>(p))
#define F4(p)  (*reinterpret_cast<float4*>(p))

__device__ __forceinline__ ull pack2(float x, float y) {
    ull p; asm("mov.b64 %0, {%1, %2};" : "=l"(p) : "f"(x), "f"(y)); return p;
}
__device__ __forceinline__ void unpack2(ull p, float& x, float& y) {
    asm("mov.b64 {%0, %1}, %2;" : "=f"(x), "=f"(y) : "l"(p));
}
__device__ __forceinline__ void ffma2(ull& d, ull a, ull b) {
    asm("fma.rn.f32x2 %0, %1, %2, %0;" : "+l"(d) : "l"(a), "l"(b));
}

// ---- pack kernel: gather 12 weight buffers into pair-major staging ----
__global__ void pack_weights_kernel(
    const float* __restrict__ Wq, const float* __restrict__ bq,
    const float* __restrict__ Wk, const float* __restrict__ bk,
    const float* __restrict__ Wv, const float* __restrict__ bv,
    const float* __restrict__ Wo, const float* __restrict__ bo,
    const float* __restrict__ W1, const float* __restrict__ b1,
    const float* __restrict__ W2, const float* __restrict__ b2)
{
    const int t = threadIdx.x;
    for (int i = t; i < 72; i += 256) {
        int e = i / 6, p = i % 6;
        gStage.pWq[i] = pack2(Wq[(2*p) * D + e], Wq[(2*p+1) * D + e]);
        gStage.pWk[i] = pack2(Wk[(2*p) * D + e], Wk[(2*p+1) * D + e]);
        gStage.pWv[i] = pack2(Wv[(2*p) * D + e], Wv[(2*p+1) * D + e]);
        gStage.pWo[i] = pack2(Wo[(2*p) * D + e], Wo[(2*p+1) * D + e]);
    }
    for (int i = t; i < 144; i += 256) {
        int e = i / 12, p = i % 12;
        gStage.pW1[i] = pack2(W1[(2*p) * D + e], W1[(2*p+1) * D + e]);
    }
    for (int i = t; i < 144; i += 256) {
        int f = i / 6, p = i % 6;
        gStage.pW2[i] = pack2(W2[(2*p) * F + f], W2[(2*p+1) * F + f]);
    }
    if (t < 6) {
        gStage.pbq[t] = pack2(bq[2*t], bq[2*t+1]);
        gStage.pbk[t] = pack2(bk[2*t], bk[2*t+1]);
        gStage.pbv[t] = pack2(bv[2*t], bv[2*t+1]);
        gStage.pbo[t] = pack2(bo[2*t], bo[2*t+1]);
        gStage.pb2[t] = pack2(b2[2*t], b2[2*t+1]);
    }
    if (t < 12) gStage.pb1[t] = pack2(b1[2*t], b1[2*t+1]);
}

__global__ __launch_bounds__(THREADS, 4)
void tiny_transformer_kernel(
    const int*   __restrict__ x,
    const float* __restrict__ embed,
    const float* __restrict__ pos,
    const float* __restrict__ blm,
    float* __restrict__ out)
{
    // ---- shared: only lane-divergent data ----
    __shared__ __align__(16) float sEmb[V * D];    // natural [v][d] for gather
    __shared__ __align__(16) float sEmbT[D * V];   // transposed [d][v] for logits
    __shared__ __align__(16) float sPos[N * D];
    __shared__ __align__(16) float sBlm[V];
    __shared__ __align__(16) float sXf[WARPS][4 * N * D];

    const int tid = threadIdx.x;

    for (int i = tid; i < V * D; i += THREADS) sEmb[i] = embed[i];
    for (int i = tid; i < D * V; i += THREADS) {
        int d = i >> 7, v = i & 127;
        sEmbT[i] = embed[v * D + d];
    }
    for (int i = tid; i < N * D; i += THREADS) sPos[i] = pos[i];
    for (int i = tid; i < V; i += THREADS) sBlm[i] = blm[i];
    __syncthreads();

    const int w    = tid >> 5;
    const int lane = tid & 31;
    const int n    = lane & 7;
    const int item_base = blockIdx.x * ITEMS_PER_BLOCK + w * 4;

    // ---- phase 1: X = embed[x] + pos ----
    const int tok = __ldg(&x[item_base * N + lane]);
    float X[D];
    #pragma unroll
    for (int c = 0; c < 3; c++) {
        float4 e = F4C(&sEmb[tok * D + 4 * c]);
        float4 p = F4C(&sPos[n * D + 4 * c]);
        X[4*c+0] = e.x + p.x; X[4*c+1] = e.y + p.y;
        X[4*c+2] = e.z + p.z; X[4*c+3] = e.w + p.w;
    }

    // ---- phase 2: Q,K,V (packed FFMA2 against constant port) ----
    float Qr[D], Kr[D], Vr[D];
    {
        ull q2[6], k2[6], v2[6];
        #pragma unroll
        for (int p = 0; p < 6; p++) {
            q2[p] = cw.pbq[p]; k2[p] = cw.pbk[p]; v2[p] = cw.pbv[p];
        }
        #pragma unroll
        for (int e = 0; e < D; e++) {
            const ull xp = pack2(X[e], X[e]);
            #pragma unroll
            for (int p = 0; p < 6; p++) {
                ffma2(q2[p], xp, cw.pWq[e * 6 + p]);
                ffma2(k2[p], xp, cw.pWk[e * 6 + p]);
                ffma2(v2[p], xp, cw.pWv[e * 6 + p]);
            }
        }
        #pragma unroll
        for (int p = 0; p < 6; p++) {
            unpack2(q2[p], Qr[2*p], Qr[2*p+1]);
            unpack2(k2[p], Kr[2*p], Kr[2*p+1]);
            unpack2(v2[p], Vr[2*p], Vr[2*p+1]);
        }
    }

    // ---- phase 3: scores via width-8 shuffles ----
    float S[N];
    {
        const float inv_scale = 0.28867513459481287f;  // 1/sqrt(12)
        #pragma unroll
        for (int m = 0; m < N; m++) {
            float acc = 0.f;
            #pragma unroll
            for (int e = 0; e < D; e++)
                acc += Qr[e] * __shfl_sync(0xffffffffu, Kr[e], m, 8);
            S[m] = (m <= n) ? acc * inv_scale : -1e30f;
        }
    }

    // ---- phase 4: softmax ----
    {
        float mx = S[0];
        #pragma unroll
        for (int m = 1; m < N; m++) mx = fmaxf(mx, S[m]);
        float sum = 0.f;
        #pragma unroll
        for (int m = 0; m < N; m++) { S[m] = __expf(S[m] - mx); sum += S[m]; }
        const float inv = 1.f / sum;
        #pragma unroll
        for (int m = 0; m < N; m++) S[m] *= inv;
    }

    // ---- phase 5: A = softmax @ V via shuffles ----
    float A[D];
    #pragma unroll
    for (int e = 0; e < D; e++) A[e] = 0.f;
    #pragma unroll
    for (int m = 0; m < N; m++) {
        const float s = S[m];
        #pragma unroll
        for (int e = 0; e < D; e++)
            A[e] += s * __shfl_sync(0xffffffffu, Vr[e], m, 8);
    }

    // ---- phase 6: X += A @ Wo^T + bo (packed) ----
    {
        ull o2[6];
        #pragma unroll
        for (int p = 0; p < 6; p++) o2[p] = cw.pbo[p];
        #pragma unroll
        for (int e = 0; e < D; e++) {
            const ull ap = pack2(A[e], A[e]);
            #pragma unroll
            for (int p = 0; p < 6; p++)
                ffma2(o2[p], ap, cw.pWo[e * 6 + p]);
        }
        #pragma unroll
        for (int p = 0; p < 6; p++) {
            float u, v; unpack2(o2[p], u, v);
            X[2*p] += u; X[2*p+1] += v;
        }
    }

    // ---- phase 7: H = relu(X @ W1^T + b1) (packed) ----
    float H[F];
    {
        ull h2[12];
        #pragma unroll
        for (int p = 0; p < 12; p++) h2[p] = cw.pb1[p];
        #pragma unroll
        for (int e = 0; e < D; e++) {
            const ull xp = pack2(X[e], X[e]);
            #pragma unroll
            for (int p = 0; p < 12; p++)
                ffma2(h2[p], xp, cw.pW1[e * 12 + p]);
        }
        #pragma unroll
        for (int p = 0; p < 12; p++) {
            float u, v; unpack2(h2[p], u, v);
            H[2*p]   = fmaxf(u, 0.f);
            H[2*p+1] = fmaxf(v, 0.f);
        }
    }

    // ---- phase 8: X += H @ W2^T + b2 (packed) ----
    {
        ull x2[6];
        #pragma unroll
        for (int p = 0; p < 6; p++) x2[p] = cw.pb2[p];
        #pragma unroll
        for (int f = 0; f < F; f++) {
            const ull hp = pack2(H[f], H[f]);
            #pragma unroll
            for (int p = 0; p < 6; p++)
                ffma2(x2[p], hp, cw.pW2[f * 6 + p]);
        }
        #pragma unroll
        for (int p = 0; p < 6; p++) {
            float u, v; unpack2(x2[p], u, v);
            X[2*p] += u; X[2*p+1] += v;
        }
    }

    // ---- hand off final X ----
    {
        float* dst = &sXf[w][lane * D];
        F4(dst)     = make_float4(X[0], X[1], X[2],  X[3]);
        F4(dst + 4) = make_float4(X[4], X[5], X[6],  X[7]);
        F4(dst + 8) = make_float4(X[8], X[9], X[10], X[11]);
    }
    __syncwarp();

    // ---- phase 9: logits = Xf @ embed^T + b_lm ----
    // two column-half passes; each caches only 12 packed embT regs.
    {
        const float* xf = sXf[w];
        float* obase = out + (size_t)item_base * (N * V);

        #pragma unroll
        for (int pass = 0; pass < 2; pass++) {
            const int v0 = lane * 2 + pass * 64;
            ull e2[D];
            #pragma unroll
            for (int d = 0; d < D; d++) {
                const float2 e = *reinterpret_cast<const float2*>(&sEmbT[d * V + v0]);
                e2[d] = pack2(e.x, e.y);
            }
            const float2 bl = *reinterpret_cast<const float2*>(&sBlm[v0]);
            const ull bl2 = pack2(bl.x, bl.y);

            for (int r = 0; r < 4 * N; r++) {
                float4 xa = F4C(&xf[r * D]);      // broadcast reads
                float4 xb = F4C(&xf[r * D + 4]);
                float4 xc = F4C(&xf[r * D + 8]);
                const float xr[D] = {xa.x, xa.y, xa.z, xa.w,
                                     xb.x, xb.y, xb.z, xb.w,
                                     xc.x, xc.y, xc.z, xc.w};
                ull acc = bl2;
                #pragma unroll
                for (int d = 0; d < D; d++)
                    ffma2(acc, pack2(xr[d], xr[d]), e2[d]);
                float u, v; unpack2(acc, u, v);
                *reinterpret_cast<float2*>(&obase[(size_t)r * V + v0]) =
                    make_float2(u, v);            // warp: 256B contiguous
            }
        }
    }
}

}  // namespace

extern "C" void kernel_launch(void* const* d_in, const int* in_sizes, int n_in,
                              void* d_out, int out_size)
{
    const int*   x     = (const int*)  d_in[0];
    const float* embed = (const float*)d_in[1];
    const float* pos   = (const float*)d_in[2];
    const float* blm   = (const float*)d_in[15];
    float* out = (float*)d_out;

    // 1) gather + pair-pack all weights into staging (one kernel node)
    pack_weights_kernel<<<1, 256>>>(
        (const float*)d_in[3],  (const float*)d_in[4],
        (const float*)d_in[5],  (const float*)d_in[6],
        (const float*)d_in[7],  (const float*)d_in[8],
        (const float*)d_in[9],  (const float*)d_in[10],
        (const float*)d_in[11], (const float*)d_in[12],
        (const float*)d_in[13], (const float*)d_in[14]);

    // 2) one D2D copy staging -> constant bank (one memcpy node)
    void *dstC, *srcG;
    cudaGetSymbolAddress(&dstC, cw);
    cudaGetSymbolAddress(&srcG, gStage);
    cudaMemcpyAsync(dstC, srcG, sizeof(ConstW), cudaMemcpyDeviceToDevice);

    // 3) main kernel
    const int batch  = in_sizes[0] / N;              // 32768
    const int blocks = batch / ITEMS_PER_BLOCK;      // 1024

    tiny_transformer_kernel<<<blocks, THREADS>>>(x, embed, pos, blm, out);
}